// round 10
// baseline (speedup 1.0000x reference)
#include <cuda_runtime.h>
#include <cuda_fp16.h>
#include <mma.h>
#include <cstdint>

using namespace nvcuda;

#define NTOK 2048
#define DDIM 512
#define HDIM 2048
#define GNUM 4
#define EPG  4
#define ENUM 16
#define GTP_THR 0.9f
#define TP_THR  0.9f
#define SCALE_W 0.5f

// ---------------- scratch ----------------
__device__ float d_tw[NTOK * ENUM];
__device__ int   d_slot[NTOK * ENUM];
__device__ int   d_bucket_tok[ENUM * NTOK];
__device__ float d_bucket_w[ENUM * NTOK];
__device__ int   d_counts[ENUM];
__device__ __half d_h16[(size_t)ENUM * NTOK * HDIM];    // 128 MB
__device__ float d_partial[(size_t)ENUM * NTOK * DDIM]; // 64 MB

// ---------------- helpers ----------------
__device__ __forceinline__ void cvthi4(float4 v, __half* hi) {
    ((__half2*)hi)[0] = __floats2half2_rn(v.x, v.y);
    ((__half2*)hi)[1] = __floats2half2_rn(v.z, v.w);
}

// ---------------- routing ----------------
__device__ __forceinline__ void top2norm(const float* logit, float thr, float* w) {
    float m = logit[0];
    #pragma unroll
    for (int i = 1; i < 4; i++) m = fmaxf(m, logit[i]);
    float p[4], s = 0.f;
    #pragma unroll
    for (int i = 0; i < 4; i++) { p[i] = expf(logit[i] - m); s += p[i]; }
    #pragma unroll
    for (int i = 0; i < 4; i++) p[i] /= s;
    int i0 = 0; float b0 = p[0];
    #pragma unroll
    for (int i = 1; i < 4; i++) if (p[i] > b0) { b0 = p[i]; i0 = i; }
    int i1 = -1; float b1 = -1.f;
    #pragma unroll
    for (int i = 0; i < 4; i++) if (i != i0 && p[i] > b1) { b1 = p[i]; i1 = i; }
    bool act1 = (b0 + b1) <= thr;
    float mp1 = act1 ? b1 : 0.f;
    float den = b0 + mp1 + 1e-9f;
    #pragma unroll
    for (int i = 0; i < 4; i++) w[i] = 0.f;
    w[i0] = b0 / den;
    w[i1] = mp1 / den;
}

__global__ __launch_bounds__(256) void routing_kernel(
    const float* __restrict__ x, const float* __restrict__ Wr,
    const float* __restrict__ br, const float* __restrict__ Wg,
    const float* __restrict__ bg)
{
    int wid = threadIdx.x >> 5, lane = threadIdx.x & 31;
    int n = blockIdx.x * 8 + wid;
    const float* xr = x + (size_t)n * DDIM;
    float xv[16];
    #pragma unroll
    for (int i = 0; i < 16; i++) xv[i] = xr[lane + 32 * i];

    float acc[20];
    #pragma unroll
    for (int g = 0; g < 4; g++) {
        float s = 0.f;
        #pragma unroll
        for (int i = 0; i < 16; i++) s += xv[i] * Wr[(lane + 32 * i) * 4 + g];
        acc[g] = s;
    }
    #pragma unroll
    for (int g = 0; g < 4; g++) {
        #pragma unroll
        for (int e = 0; e < 4; e++) {
            float s = 0.f;
            const float* wgp = Wg + (size_t)g * DDIM * EPG + e;
            #pragma unroll
            for (int i = 0; i < 16; i++) s += xv[i] * wgp[(lane + 32 * i) * 4];
            acc[4 + g * 4 + e] = s;
        }
    }
    #pragma unroll
    for (int o = 16; o; o >>= 1) {
        #pragma unroll
        for (int j = 0; j < 20; j++) acc[j] += __shfl_xor_sync(0xffffffffu, acc[j], o);
    }
    if (lane == 0) {
        float gl[4];
        #pragma unroll
        for (int g = 0; g < 4; g++) gl[g] = acc[g] + br[g];
        float wgrp[4];
        top2norm(gl, GTP_THR, wgrp);
        #pragma unroll
        for (int g = 0; g < 4; g++) {
            float el[4];
            #pragma unroll
            for (int e = 0; e < 4; e++) el[e] = acc[4 + g * 4 + e] + bg[g * 4 + e];
            float wexp[4];
            top2norm(el, TP_THR, wexp);
            #pragma unroll
            for (int e = 0; e < 4; e++) {
                d_tw[n * ENUM + g * 4 + e] = wgrp[g] * wexp[e] * SCALE_W;
                d_slot[n * ENUM + g * 4 + e] = -1;
            }
        }
    }
}

// ---------------- bucket build ----------------
__global__ __launch_bounds__(256) void build_buckets() {
    int e = blockIdx.x;
    int t = threadIdx.x;
    __shared__ int sc[256];
    int base = t * 8;
    float wv[8];
    int flags = 0, cnt = 0;
    #pragma unroll
    for (int j = 0; j < 8; j++) {
        float v = d_tw[(base + j) * ENUM + e];
        wv[j] = v;
        if (v > 0.f) { flags |= 1 << j; cnt++; }
    }
    sc[t] = cnt;
    __syncthreads();
    for (int off = 1; off < 256; off <<= 1) {
        int v = sc[t];
        int add = (t >= off) ? sc[t - off] : 0;
        __syncthreads();
        sc[t] = v + add;
        __syncthreads();
    }
    int pos = sc[t] - cnt;
    #pragma unroll
    for (int j = 0; j < 8; j++) {
        if ((flags >> j) & 1) {
            int n = base + j;
            d_bucket_tok[e * NTOK + pos] = n;
            d_bucket_w[e * NTOK + pos] = wv[j];
            d_slot[n * ENUM + e] = pos;
            pos++;
        }
    }
    if (t == 255) d_counts[e] = sc[255];
}

// =============================================================================
// wmma_up: block 128(M) x 64(N) producing u AND v. K-chunk 32, 16 chunks.
// Warp-specialized: warps 0-3 = consumers (warp tile 64x32 for u and v),
// warps 4-7 = producers (LDG + fp16 convert + STS, register-prefetched).
// SMEM halfs/buffer: Ah[128x40]@0  B1h[32x72]@5120  B3h[32x72]@7424 (9728)
// =============================================================================
__global__ __launch_bounds__(256, 1) void wmma_up(
    const float* __restrict__ x, const float* __restrict__ W1,
    const float* __restrict__ W3)
{
    __shared__ __align__(16) __half SM[2][9728];   // 38912 B
    int e = blockIdx.z;
    int cnt = d_counts[e];
    if (cnt == 0) return;
    int cntp = (cnt + 127) & ~127;
    int m0 = blockIdx.y * 128;
    if (m0 >= cntp) return;
    int n0 = blockIdx.x * 64;
    int tid = threadIdx.x, lane = tid & 31, wid = tid >> 5;
    const int NK = DDIM / 32;

    if (wid >= 4) {
        // ---------------- producer ----------------
        int pt = tid & 127;
        int gi = m0 + pt; if (gi > cnt - 1) gi = cnt - 1;
        const float* xrow = x + (size_t)d_bucket_tok[e * NTOK + gi] * DDIM;
        int kb = pt >> 2, cb = (pt & 3) * 16;
        const float* w1p = W1 + (size_t)e * DDIM * HDIM + (size_t)kb * HDIM + n0 + cb;
        const float* w3p = W3 + (size_t)e * DDIM * HDIM + (size_t)kb * HDIM + n0 + cb;

        float4 rA[8], rB1[4], rB3[4];
        auto ldreg = [&](int kc) {
            int k0 = kc * 32;
            #pragma unroll
            for (int q = 0; q < 8; q++) rA[q] = *(const float4*)(xrow + k0 + q * 4);
            #pragma unroll
            for (int q = 0; q < 4; q++) {
                rB1[q] = *(const float4*)(w1p + (size_t)k0 * HDIM + q * 4);
                rB3[q] = *(const float4*)(w3p + (size_t)k0 * HDIM + q * 4);
            }
        };
        auto sts = [&](int b) {
            __half* Ah = SM[b];
            #pragma unroll
            for (int q = 0; q < 8; q++) cvthi4(rA[q], Ah + pt * 40 + q * 4);
            __half* B1h = SM[b] + 5120;
            __half* B3h = SM[b] + 7424;
            #pragma unroll
            for (int q = 0; q < 4; q++) {
                cvthi4(rB1[q], B1h + kb * 72 + cb + q * 4);
                cvthi4(rB3[q], B3h + kb * 72 + cb + q * 4);
            }
        };
        ldreg(0); sts(0);
        ldreg(1);
        __syncthreads();
        for (int kc = 0; kc < NK; kc++) {
            if (kc + 1 < NK) sts((kc + 1) & 1);
            if (kc + 2 < NK) ldreg(kc + 2);
            __syncthreads();
        }
        return;   // consumers use only __syncwarp past this point
    }

    // ---------------- consumer ----------------
    int wm = wid & 1, wn = wid >> 1;
    wmma::fragment<wmma::accumulator, 16, 16, 16, float> u[4][2], v[4][2];
    #pragma unroll
    for (int i = 0; i < 4; i++)
        #pragma unroll
        for (int j = 0; j < 2; j++) {
            wmma::fill_fragment(u[i][j], 0.0f);
            wmma::fill_fragment(v[i][j], 0.0f);
        }
    __syncthreads();   // matches producer prologue sync
    for (int kc = 0; kc < NK; kc++) {
        int b = kc & 1;
        __half* Ah = SM[b];
        __half* B1h = SM[b] + 5120;
        __half* B3h = SM[b] + 7424;
        #pragma unroll
        for (int ks = 0; ks < 2; ks++) {
            wmma::fragment<wmma::matrix_a, 16, 16, 16, __half, wmma::row_major> fa[4];
            #pragma unroll
            for (int i = 0; i < 4; i++)
                wmma::load_matrix_sync(fa[i], Ah + (wm * 64 + 16 * i) * 40 + ks * 16, 40);
            wmma::fragment<wmma::matrix_b, 16, 16, 16, __half, wmma::row_major> f1[2], f3[2];
            #pragma unroll
            for (int j = 0; j < 2; j++) {
                int bo = ks * 16 * 72 + wn * 32 + 16 * j;
                wmma::load_matrix_sync(f1[j], B1h + bo, 72);
                wmma::load_matrix_sync(f3[j], B3h + bo, 72);
            }
            #pragma unroll
            for (int i = 0; i < 4; i++)
                #pragma unroll
                for (int j = 0; j < 2; j++) {
                    wmma::mma_sync(u[i][j], fa[i], f1[j], u[i][j]);
                    wmma::mma_sync(v[i][j], fa[i], f3[j], v[i][j]);
                }
        }
        __syncthreads();
    }

    // epilogue: h = silu(u)*v -> fp16
    float* epi = (float*)SM + wid * 576;
    int r = lane >> 1, c0 = (lane & 1) * 8;
    #pragma unroll
    for (int i = 0; i < 4; i++)
        #pragma unroll
        for (int j = 0; j < 2; j++) {
            #pragma unroll
            for (int t = 0; t < u[i][j].num_elements; t++) {
                float uu = u[i][j].x[t];
                u[i][j].x[t] = uu / (1.f + __expf(-uu)) * v[i][j].x[t];
            }
            wmma::store_matrix_sync(epi, u[i][j], 36, wmma::mem_row_major);
            __syncwarp();
            int grow = m0 + wm * 64 + 16 * i + r;
            int gcol = n0 + wn * 32 + 16 * j + c0;
            __half2* op = (__half2*)(d_h16 + ((size_t)e * NTOK + grow) * HDIM + gcol);
            #pragma unroll
            for (int q = 0; q < 4; q++)
                op[q] = __floats2half2_rn(epi[r * 36 + c0 + 2 * q],
                                          epi[r * 36 + c0 + 2 * q + 1]);
            __syncwarp();
        }
}

// =============================================================================
// wmma_down: block 128(M) x 128(N). K-chunk 32, 64 chunks.
// Warp-specialized: warps 0-3 consumers (warp 64x64), warps 4-7 producers.
// A (h) is fp16 in global: producer copies raw uint4 (no conversion).
// SMEM halfs/buffer: Ah[128x40]@0  Bh[32x136]@5120  (9472)
// =============================================================================
__global__ __launch_bounds__(256, 1) void wmma_down(const float* __restrict__ W2)
{
    __shared__ __align__(16) __half SM[2][9472];   // 37888 B
    int e = blockIdx.z;
    int cnt = d_counts[e];
    if (cnt == 0) return;
    int cntp = (cnt + 127) & ~127;
    int m0 = blockIdx.y * 128;
    if (m0 >= cntp) return;
    int n0 = blockIdx.x * 128;
    int tid = threadIdx.x, lane = tid & 31, wid = tid >> 5;
    const int NK = HDIM / 32;

    if (wid >= 4) {
        // ---------------- producer ----------------
        int pt = tid & 127;
        const __half* arow = d_h16 + ((size_t)e * NTOK + m0 + pt) * HDIM;
        int kb = pt >> 2, cb = (pt & 3) * 32;
        const float* w2p = W2 + (size_t)e * HDIM * DDIM + (size_t)kb * DDIM + n0 + cb;

        uint4 rA[4];
        float4 rB[8];
        auto ldreg = [&](int kc) {
            int k0 = kc * 32;
            #pragma unroll
            for (int q = 0; q < 4; q++) rA[q] = *(const uint4*)(arow + k0 + q * 8);
            #pragma unroll
            for (int q = 0; q < 8; q++) rB[q] = *(const float4*)(w2p + (size_t)k0 * DDIM + q * 4);
        };
        auto sts = [&](int b) {
            __half* Ah = SM[b];
            #pragma unroll
            for (int q = 0; q < 4; q++)
                *(uint4*)(Ah + pt * 40 + q * 8) = rA[q];
            __half* Bh = SM[b] + 5120;
            #pragma unroll
            for (int q = 0; q < 8; q++)
                cvthi4(rB[q], Bh + kb * 136 + cb + q * 4);
        };
        ldreg(0); sts(0);
        ldreg(1);
        __syncthreads();
        for (int kc = 0; kc < NK; kc++) {
            if (kc + 1 < NK) sts((kc + 1) & 1);
            if (kc + 2 < NK) ldreg(kc + 2);
            __syncthreads();
        }
        return;
    }

    // ---------------- consumer ----------------
    int wm = wid & 1, wn = wid >> 1;
    wmma::fragment<wmma::accumulator, 16, 16, 16, float> c[4][4];
    #pragma unroll
    for (int i = 0; i < 4; i++)
        #pragma unroll
        for (int j = 0; j < 4; j++) wmma::fill_fragment(c[i][j], 0.0f);
    __syncthreads();
    for (int kc = 0; kc < NK; kc++) {
        int b = kc & 1;
        __half* Ah = SM[b];
        __half* Bh = SM[b] + 5120;
        #pragma unroll
        for (int ks = 0; ks < 2; ks++) {
            wmma::fragment<wmma::matrix_a, 16, 16, 16, __half, wmma::row_major> fa[4];
            #pragma unroll
            for (int i = 0; i < 4; i++)
                wmma::load_matrix_sync(fa[i], Ah + (wm * 64 + 16 * i) * 40 + ks * 16, 40);
            wmma::fragment<wmma::matrix_b, 16, 16, 16, __half, wmma::row_major> fb[4];
            #pragma unroll
            for (int j = 0; j < 4; j++)
                wmma::load_matrix_sync(fb[j], Bh + ks * 16 * 136 + wn * 64 + 16 * j, 136);
            #pragma unroll
            for (int i = 0; i < 4; i++)
                #pragma unroll
                for (int j = 0; j < 4; j++)
                    wmma::mma_sync(c[i][j], fa[i], fb[j], c[i][j]);
        }
        __syncthreads();
    }

    float* epi = (float*)SM + wid * 576;
    int r = lane >> 1, c0 = (lane & 1) * 8;
    #pragma unroll
    for (int i = 0; i < 4; i++)
        #pragma unroll
        for (int j = 0; j < 4; j++) {
            wmma::store_matrix_sync(epi, c[i][j], 36, wmma::mem_row_major);
            __syncwarp();
            int grow = m0 + wm * 64 + 16 * i + r;
            float w = d_bucket_w[e * NTOK + grow];
            int gcol = n0 + wn * 64 + 16 * j + c0;
            float* op = d_partial + ((size_t)e * NTOK + grow) * DDIM + gcol;
            float4 o0 = { epi[r * 36 + c0] * w,     epi[r * 36 + c0 + 1] * w,
                          epi[r * 36 + c0 + 2] * w, epi[r * 36 + c0 + 3] * w };
            float4 o1 = { epi[r * 36 + c0 + 4] * w, epi[r * 36 + c0 + 5] * w,
                          epi[r * 36 + c0 + 6] * w, epi[r * 36 + c0 + 7] * w };
            *(float4*)op = o0;
            *(float4*)(op + 4) = o1;
            __syncwarp();
        }
}

// ---------------- gather ----------------
__global__ __launch_bounds__(128) void gather_out(float* __restrict__ out) {
    int n = blockIdx.x;
    int tid = threadIdx.x;
    float acc[4] = {0.f, 0.f, 0.f, 0.f};
    #pragma unroll
    for (int e = 0; e < ENUM; e++) {
        int s = d_slot[n * ENUM + e];
        if (s >= 0) {
            const float* pp = d_partial + ((size_t)e * NTOK + s) * DDIM;
            #pragma unroll
            for (int q = 0; q < 4; q++) acc[q] += pp[tid + q * 128];
        }
    }
    #pragma unroll
    for (int q = 0; q < 4; q++) out[(size_t)n * DDIM + tid + q * 128] = acc[q];
}

// ---------------- launch ----------------
extern "C" void kernel_launch(void* const* d_in, const int* in_sizes, int n_in,
                              void* d_out, int out_size)
{
    const float* x  = (const float*)d_in[0];
    const float* Wr = (const float*)d_in[1];
    const float* br = (const float*)d_in[2];
    const float* Wg = (const float*)d_in[3];
    const float* bg = (const float*)d_in[4];
    const float* W1 = (const float*)d_in[5];
    const float* W3 = (const float*)d_in[6];
    const float* W2 = (const float*)d_in[7];
    float* out = (float*)d_out;

    routing_kernel<<<NTOK / 8, 256>>>(x, Wr, br, Wg, bg);              // 1
    build_buckets<<<ENUM, 256>>>();                                     // 2
    wmma_up<<<dim3(HDIM / 64, NTOK / 128, ENUM), 256>>>(x, W1, W3);    // 3
    wmma_down<<<dim3(DDIM / 128, NTOK / 128, ENUM), 256>>>(W2);        // 4 <- ncu
    gather_out<<<NTOK, 128>>>(out);                                     // 5
}

// round 11
// speedup vs baseline: 1.1134x; 1.1134x over previous
#include <cuda_runtime.h>
#include <cuda_fp16.h>
#include <mma.h>
#include <cstdint>

using namespace nvcuda;

#define NTOK 2048
#define DDIM 512
#define HDIM 2048
#define GNUM 4
#define EPG  4
#define ENUM 16
#define GTP_THR 0.9f
#define TP_THR  0.9f
#define SCALE_W 0.5f

// ---------------- scratch ----------------
__device__ float d_tw[NTOK * ENUM];
__device__ int   d_slot[NTOK * ENUM];
__device__ int   d_bucket_tok[ENUM * NTOK];
__device__ float d_bucket_w[ENUM * NTOK];
__device__ int   d_counts[ENUM];
__device__ __half d_h16[(size_t)ENUM * NTOK * HDIM];    // 128 MB
__device__ float d_partial[(size_t)ENUM * NTOK * DDIM]; // 64 MB

// ---------------- helpers ----------------
__device__ __forceinline__ void cvthi4(float4 v, __half* hi) {
    ((__half2*)hi)[0] = __floats2half2_rn(v.x, v.y);
    ((__half2*)hi)[1] = __floats2half2_rn(v.z, v.w);
}

// ---------------- routing ----------------
__device__ __forceinline__ void top2norm(const float* logit, float thr, float* w) {
    float m = logit[0];
    #pragma unroll
    for (int i = 1; i < 4; i++) m = fmaxf(m, logit[i]);
    float p[4], s = 0.f;
    #pragma unroll
    for (int i = 0; i < 4; i++) { p[i] = expf(logit[i] - m); s += p[i]; }
    #pragma unroll
    for (int i = 0; i < 4; i++) p[i] /= s;
    int i0 = 0; float b0 = p[0];
    #pragma unroll
    for (int i = 1; i < 4; i++) if (p[i] > b0) { b0 = p[i]; i0 = i; }
    int i1 = -1; float b1 = -1.f;
    #pragma unroll
    for (int i = 0; i < 4; i++) if (i != i0 && p[i] > b1) { b1 = p[i]; i1 = i; }
    bool act1 = (b0 + b1) <= thr;
    float mp1 = act1 ? b1 : 0.f;
    float den = b0 + mp1 + 1e-9f;
    #pragma unroll
    for (int i = 0; i < 4; i++) w[i] = 0.f;
    w[i0] = b0 / den;
    w[i1] = mp1 / den;
}

__global__ __launch_bounds__(256) void routing_kernel(
    const float* __restrict__ x, const float* __restrict__ Wr,
    const float* __restrict__ br, const float* __restrict__ Wg,
    const float* __restrict__ bg)
{
    int wid = threadIdx.x >> 5, lane = threadIdx.x & 31;
    int n = blockIdx.x * 8 + wid;
    const float* xr = x + (size_t)n * DDIM;
    float xv[16];
    #pragma unroll
    for (int i = 0; i < 16; i++) xv[i] = xr[lane + 32 * i];

    float acc[20];
    #pragma unroll
    for (int g = 0; g < 4; g++) {
        float s = 0.f;
        #pragma unroll
        for (int i = 0; i < 16; i++) s += xv[i] * Wr[(lane + 32 * i) * 4 + g];
        acc[g] = s;
    }
    #pragma unroll
    for (int g = 0; g < 4; g++) {
        #pragma unroll
        for (int e = 0; e < 4; e++) {
            float s = 0.f;
            const float* wgp = Wg + (size_t)g * DDIM * EPG + e;
            #pragma unroll
            for (int i = 0; i < 16; i++) s += xv[i] * wgp[(lane + 32 * i) * 4];
            acc[4 + g * 4 + e] = s;
        }
    }
    #pragma unroll
    for (int o = 16; o; o >>= 1) {
        #pragma unroll
        for (int j = 0; j < 20; j++) acc[j] += __shfl_xor_sync(0xffffffffu, acc[j], o);
    }
    if (lane == 0) {
        float gl[4];
        #pragma unroll
        for (int g = 0; g < 4; g++) gl[g] = acc[g] + br[g];
        float wgrp[4];
        top2norm(gl, GTP_THR, wgrp);
        #pragma unroll
        for (int g = 0; g < 4; g++) {
            float el[4];
            #pragma unroll
            for (int e = 0; e < 4; e++) el[e] = acc[4 + g * 4 + e] + bg[g * 4 + e];
            float wexp[4];
            top2norm(el, TP_THR, wexp);
            #pragma unroll
            for (int e = 0; e < 4; e++) {
                d_tw[n * ENUM + g * 4 + e] = wgrp[g] * wexp[e] * SCALE_W;
                d_slot[n * ENUM + g * 4 + e] = -1;
            }
        }
    }
}

// ---------------- bucket build ----------------
__global__ __launch_bounds__(256) void build_buckets() {
    int e = blockIdx.x;
    int t = threadIdx.x;
    __shared__ int sc[256];
    int base = t * 8;
    float wv[8];
    int flags = 0, cnt = 0;
    #pragma unroll
    for (int j = 0; j < 8; j++) {
        float v = d_tw[(base + j) * ENUM + e];
        wv[j] = v;
        if (v > 0.f) { flags |= 1 << j; cnt++; }
    }
    sc[t] = cnt;
    __syncthreads();
    for (int off = 1; off < 256; off <<= 1) {
        int v = sc[t];
        int add = (t >= off) ? sc[t - off] : 0;
        __syncthreads();
        sc[t] = v + add;
        __syncthreads();
    }
    int pos = sc[t] - cnt;
    #pragma unroll
    for (int j = 0; j < 8; j++) {
        if ((flags >> j) & 1) {
            int n = base + j;
            d_bucket_tok[e * NTOK + pos] = n;
            d_bucket_w[e * NTOK + pos] = wv[j];
            d_slot[n * ENUM + e] = pos;
            pos++;
        }
    }
    if (t == 255) d_counts[e] = sc[255];
}

// =============================================================================
// wmma_up: block 256(M) x 64(N) for BOTH u=xW1 and v=xW3. K-chunk 16, 32 chunks.
// 8 warps (4m x 2n), warp tile 64x32 per output matrix. All warps stage + MMA
// (R9 pattern), double-buffered, 1 sync/chunk, register prefetch.
// SMEM halfs/buffer: Ah[256x24]@0  B1h[16x72]@6144  B3h[16x72]@7296  (8448)
// =============================================================================
__global__ __launch_bounds__(256, 1) void wmma_up(
    const float* __restrict__ x, const float* __restrict__ W1,
    const float* __restrict__ W3)
{
    __shared__ __align__(16) __half SM[2][8448];   // 33792 B
    int e = blockIdx.z;
    int cnt = d_counts[e];
    if (cnt == 0) return;
    int cntp = (cnt + 127) & ~127;
    int m0 = blockIdx.y * 256;
    if (m0 >= cntp) return;
    int n0 = blockIdx.x * 64;
    int tid = threadIdx.x, lane = tid & 31, wid = tid >> 5;
    const int NK = DDIM / 16;

    // staging mappings
    int gi = m0 + tid; if (gi > cnt - 1) gi = cnt - 1;
    const float* xrow = x + (size_t)d_bucket_tok[e * NTOK + gi] * DDIM;
    int kB = tid >> 4, cB = (tid & 15) * 4;   // B: 16 k-rows x 16 col-groups
    const float* w1p = W1 + (size_t)e * DDIM * HDIM + (size_t)kB * HDIM + n0 + cB;
    const float* w3p = W3 + (size_t)e * DDIM * HDIM + (size_t)kB * HDIM + n0 + cB;

    float4 rA[4], rB1, rB3;
    auto ldreg = [&](int kc) {
        int k0 = kc * 16;
        #pragma unroll
        for (int q = 0; q < 4; q++) rA[q] = *(const float4*)(xrow + k0 + q * 4);
        rB1 = *(const float4*)(w1p + (size_t)k0 * HDIM);
        rB3 = *(const float4*)(w3p + (size_t)k0 * HDIM);
    };
    auto sts = [&](int b) {
        __half* Ah = SM[b];
        #pragma unroll
        for (int q = 0; q < 4; q++) cvthi4(rA[q], Ah + tid * 24 + q * 4);
        cvthi4(rB1, SM[b] + 6144 + kB * 72 + cB);
        cvthi4(rB3, SM[b] + 7296 + kB * 72 + cB);
    };

    int wm = wid & 3, wn = wid >> 2;
    wmma::fragment<wmma::accumulator, 16, 16, 16, float> u[4][2], v[4][2];
    #pragma unroll
    for (int i = 0; i < 4; i++)
        #pragma unroll
        for (int j = 0; j < 2; j++) {
            wmma::fill_fragment(u[i][j], 0.0f);
            wmma::fill_fragment(v[i][j], 0.0f);
        }

    ldreg(0);
    for (int kc = 0; kc < NK; kc++) {
        int b = kc & 1;
        sts(b);
        if (kc + 1 < NK) ldreg(kc + 1);
        __syncthreads();
        __half* Ah = SM[b];
        __half* B1h = SM[b] + 6144;
        __half* B3h = SM[b] + 7296;
        wmma::fragment<wmma::matrix_a, 16, 16, 16, __half, wmma::row_major> fa[4];
        #pragma unroll
        for (int i = 0; i < 4; i++)
            wmma::load_matrix_sync(fa[i], Ah + (wm * 64 + 16 * i) * 24, 24);
        wmma::fragment<wmma::matrix_b, 16, 16, 16, __half, wmma::row_major> f1[2], f3[2];
        #pragma unroll
        for (int j = 0; j < 2; j++) {
            wmma::load_matrix_sync(f1[j], B1h + wn * 32 + 16 * j, 72);
            wmma::load_matrix_sync(f3[j], B3h + wn * 32 + 16 * j, 72);
        }
        #pragma unroll
        for (int i = 0; i < 4; i++)
            #pragma unroll
            for (int j = 0; j < 2; j++) {
                wmma::mma_sync(u[i][j], fa[i], f1[j], u[i][j]);
                wmma::mma_sync(v[i][j], fa[i], f3[j], v[i][j]);
            }
        // no trailing sync: buffer b is rewritten at kc+2, separated by the
        // sync at kc+1 which is after every warp's kc MMA (program order).
    }
    __syncthreads();

    // epilogue: h = silu(u)*v -> fp16
    float* epi = (float*)SM + wid * 576;
    int r = lane >> 1, c0 = (lane & 1) * 8;
    #pragma unroll
    for (int i = 0; i < 4; i++)
        #pragma unroll
        for (int j = 0; j < 2; j++) {
            #pragma unroll
            for (int t = 0; t < u[i][j].num_elements; t++) {
                float uu = u[i][j].x[t];
                u[i][j].x[t] = uu / (1.f + __expf(-uu)) * v[i][j].x[t];
            }
            wmma::store_matrix_sync(epi, u[i][j], 36, wmma::mem_row_major);
            __syncwarp();
            int grow = m0 + wm * 64 + 16 * i + r;
            int gcol = n0 + wn * 32 + 16 * j + c0;
            __half2* op = (__half2*)(d_h16 + ((size_t)e * NTOK + grow) * HDIM + gcol);
            #pragma unroll
            for (int q = 0; q < 4; q++)
                op[q] = __floats2half2_rn(epi[r * 36 + c0 + 2 * q],
                                          epi[r * 36 + c0 + 2 * q + 1]);
            __syncwarp();
        }
}

// =============================================================================
// wmma_down: block 256(M) x 128(N). K-chunk 16, 128 chunks.
// 8 warps (4m x 2n), warp tile 64x64. A (h) fp16 raw-copied; B (W2) converted.
// SMEM halfs/buffer: Ah[256x24]@0  Bh[16x136]@6144  (8320)
// =============================================================================
__global__ __launch_bounds__(256, 1) void wmma_down(const float* __restrict__ W2)
{
    __shared__ __align__(16) __half SM[2][8320];   // 33280 B
    int e = blockIdx.z;
    int cnt = d_counts[e];
    if (cnt == 0) return;
    int cntp = (cnt + 127) & ~127;
    int m0 = blockIdx.y * 256;
    if (m0 >= cntp) return;
    int n0 = blockIdx.x * 128;
    int tid = threadIdx.x, lane = tid & 31, wid = tid >> 5;
    const int NK = HDIM / 16;

    const __half* arow = d_h16 + ((size_t)e * NTOK + m0 + tid) * HDIM;
    // B: 512 float4 per chunk; thread handles idx = tid and tid+256
    int k0b = tid >> 5, c0b = (tid & 31) * 4;       // idx = tid
    int k1b = (tid + 256) >> 5, c1b = ((tid + 256) & 31) * 4;
    const float* w2b = W2 + (size_t)e * HDIM * DDIM + n0;

    uint4 rA[2];
    float4 rB0, rB1;
    auto ldreg = [&](int kc) {
        int k0 = kc * 16;
        rA[0] = *(const uint4*)(arow + k0);
        rA[1] = *(const uint4*)(arow + k0 + 8);
        rB0 = *(const float4*)(w2b + (size_t)(k0 + k0b) * DDIM + c0b);
        rB1 = *(const float4*)(w2b + (size_t)(k0 + k1b) * DDIM + c1b);
    };
    auto sts = [&](int b) {
        __half* Ah = SM[b];
        *(uint4*)(Ah + tid * 24) = rA[0];
        *(uint4*)(Ah + tid * 24 + 8) = rA[1];
        __half* Bh = SM[b] + 6144;
        cvthi4(rB0, Bh + k0b * 136 + c0b);
        cvthi4(rB1, Bh + k1b * 136 + c1b);
    };

    int wm = wid & 3, wn = wid >> 2;
    wmma::fragment<wmma::accumulator, 16, 16, 16, float> c[4][4];
    #pragma unroll
    for (int i = 0; i < 4; i++)
        #pragma unroll
        for (int j = 0; j < 4; j++) wmma::fill_fragment(c[i][j], 0.0f);

    ldreg(0);
    for (int kc = 0; kc < NK; kc++) {
        int b = kc & 1;
        sts(b);
        if (kc + 1 < NK) ldreg(kc + 1);
        __syncthreads();
        __half* Ah = SM[b];
        __half* Bh = SM[b] + 6144;
        wmma::fragment<wmma::matrix_a, 16, 16, 16, __half, wmma::row_major> fa[4];
        #pragma unroll
        for (int i = 0; i < 4; i++)
            wmma::load_matrix_sync(fa[i], Ah + (wm * 64 + 16 * i) * 24, 24);
        wmma::fragment<wmma::matrix_b, 16, 16, 16, __half, wmma::row_major> fb[4];
        #pragma unroll
        for (int j = 0; j < 4; j++)
            wmma::load_matrix_sync(fb[j], Bh + wn * 64 + 16 * j, 136);
        #pragma unroll
        for (int i = 0; i < 4; i++)
            #pragma unroll
            for (int j = 0; j < 4; j++)
                wmma::mma_sync(c[i][j], fa[i], fb[j], c[i][j]);
    }
    __syncthreads();

    float* epi = (float*)SM + wid * 576;
    int r = lane >> 1, c0 = (lane & 1) * 8;
    #pragma unroll
    for (int i = 0; i < 4; i++)
        #pragma unroll
        for (int j = 0; j < 4; j++) {
            wmma::store_matrix_sync(epi, c[i][j], 36, wmma::mem_row_major);
            __syncwarp();
            int grow = m0 + wm * 64 + 16 * i + r;
            float w = d_bucket_w[e * NTOK + grow];
            int gcol = n0 + wn * 64 + 16 * j + c0;
            float* op = d_partial + ((size_t)e * NTOK + grow) * DDIM + gcol;
            float4 o0 = { epi[r * 36 + c0] * w,     epi[r * 36 + c0 + 1] * w,
                          epi[r * 36 + c0 + 2] * w, epi[r * 36 + c0 + 3] * w };
            float4 o1 = { epi[r * 36 + c0 + 4] * w, epi[r * 36 + c0 + 5] * w,
                          epi[r * 36 + c0 + 6] * w, epi[r * 36 + c0 + 7] * w };
            *(float4*)op = o0;
            *(float4*)(op + 4) = o1;
            __syncwarp();
        }
}

// ---------------- gather ----------------
__global__ __launch_bounds__(128) void gather_out(float* __restrict__ out) {
    int n = blockIdx.x;
    int tid = threadIdx.x;
    float acc[4] = {0.f, 0.f, 0.f, 0.f};
    #pragma unroll
    for (int e = 0; e < ENUM; e++) {
        int s = d_slot[n * ENUM + e];
        if (s >= 0) {
            const float* pp = d_partial + ((size_t)e * NTOK + s) * DDIM;
            #pragma unroll
            for (int q = 0; q < 4; q++) acc[q] += pp[tid + q * 128];
        }
    }
    #pragma unroll
    for (int q = 0; q < 4; q++) out[(size_t)n * DDIM + tid + q * 128] = acc[q];
}

// ---------------- launch ----------------
extern "C" void kernel_launch(void* const* d_in, const int* in_sizes, int n_in,
                              void* d_out, int out_size)
{
    const float* x  = (const float*)d_in[0];
    const float* Wr = (const float*)d_in[1];
    const float* br = (const float*)d_in[2];
    const float* Wg = (const float*)d_in[3];
    const float* bg = (const float*)d_in[4];
    const float* W1 = (const float*)d_in[5];
    const float* W3 = (const float*)d_in[6];
    const float* W2 = (const float*)d_in[7];
    float* out = (float*)d_out;

    routing_kernel<<<NTOK / 8, 256>>>(x, Wr, br, Wg, bg);              // 1
    build_buckets<<<ENUM, 256>>>();                                     // 2
    wmma_up<<<dim3(HDIM / 64, NTOK / 256, ENUM), 256>>>(x, W1, W3);    // 3
    wmma_down<<<dim3(DDIM / 128, NTOK / 256, ENUM), 256>>>(W2);        // 4 <- ncu
    gather_out<<<NTOK, 128>>>(out);                                     // 5
}